// round 9
// baseline (speedup 1.0000x reference)
#include <cuda_runtime.h>
#include <cuda_bf16.h>

// TrafficAugmentation [B=2048, S=4096] -> [B, S, 1] f32.
//
// Per row (one block, NT=256, 5 blocks/SM, static grid = B):
//  P0: stage x, dly into SMEM (float4); prefetch rtt row to L2.
//  P1: per-position delay countdown via TWO independent restart-streams per
//      thread (8 positions each, processed back-to-back; exact sequential
//      fsub chain, 4-wide batches) -> snxt[s] (u16 burst-end | kill).
//      Pairing keeps LDS latency overlapped (MLP=2); restart removes the
//      per-pair straggler waste (warp iterates max of SUMS, not sum of MAXes).
//  P2: per 32-chunk exit table via warp-shfl pointer doubling.
//  P3: serial top walk (<=128 hops) -> chain entry per chunk.
//  P4: per-chunk output-slot counts; caches (nf, rem) per burst locally.
//  P5: warp-shfl exclusive scan of chunk counts.
//  P6: pure emission of cached bursts at scanned offsets (dense, disjoint).
//  P7: store outrow[i] for i < total, else 0.

#define SS     4096
#define CHUNK  32
#define NCHUNK (SS / CHUNK)     // 128
#define MSSF   1448.0f
#define KILL16 0x8000u
#define NT     256

// Exact index-ordered sum of sx[s0..e1) via aligned float4 LDS loads;
// fp op order identical to the scalar loop (predicated edges).
__device__ __forceinline__ float burst_sum(const float* __restrict__ sxp,
                                           int s0, int e1)
{
    const float4* v4 = (const float4*)sxp;
    float buf = 0.0f;
    for (int jb = (s0 & ~3); jb < e1; jb += 4) {
        float4 v = v4[jb >> 2];
        if (jb     >= s0)                 buf = __fadd_rn(buf, v.x);
        if (jb + 1 >= s0 && jb + 1 < e1)  buf = __fadd_rn(buf, v.y);
        if (jb + 2 >= s0 && jb + 2 < e1)  buf = __fadd_rn(buf, v.z);
        if (jb + 3 >= s0 && jb + 3 < e1)  buf = __fadd_rn(buf, v.w);
    }
    return buf;
}

__global__ __launch_bounds__(NT, 5)
void traffic_kernel(const float* __restrict__ x,
                    const float* __restrict__ dly,
                    const float* __restrict__ rtt,
                    float* __restrict__ out)
{
    __shared__ __align__(16) float sx[SS + 4];   // x row + 0 pads
    __shared__ __align__(16) float sd[SS + 4];   // dly row + 1e30 pads; later:
                                                 //  P2/P3: exit table (u16)
                                                 //  P6/P7: output row (f32)
    __shared__ unsigned short snxt[SS];          // burst-end | kill
    __shared__ unsigned short senter[NCHUNK];    // chain entry per chunk
    __shared__ int swsum[NCHUNK / 32];           // per-warp count totals
    __shared__ int s_total;                      // grand output count

    const int row  = blockIdx.x;
    const size_t base = (size_t)row * SS;
    const int tid = threadIdx.x;

    // ---- P0: stage inputs; warm rtt row in L2 ----------------------------
    if (tid < NCHUNK)            // 128 x 128B lines = whole rtt row
        asm volatile("prefetch.global.L2 [%0];"
                     :: "l"(rtt + base + (size_t)tid * 32));
    {
        const float4* x4 = (const float4*)(x + base);
        const float4* d4 = (const float4*)(dly + base);
        float4* sx4 = (float4*)sx;
        float4* sd4 = (float4*)sd;
        #pragma unroll
        for (int i = tid; i < SS / 4; i += NT) { sx4[i] = x4[i]; sd4[i] = d4[i]; }
        if (tid < 4) { sx[SS + tid] = 0.0f; sd[SS + tid] = 1e30f; }
    }
    __syncthreads();

    // ---- P1: burst ends, two restart-streams per thread ------------------
    {
        // Stream A owns k = 0..7 (s = tid + k*NT), stream B owns k = 8..15.
        int  kA = -1, kB = 7;
        int  sA = 0,  sB = 0, jA = 0, jB = 0;
        float rA = 0.0f, rB = 0.0f;
        bool actA = true, actB = true;

        // advance stream: next owned position, skipping (rare) dead ones
        #define ADVANCE(kX, sX, jX, rX, actX, klim)                        \
            for (;;) {                                                     \
                if (++kX >= (klim)) { actX = false; break; }               \
                sX = tid + kX * NT;                                        \
                if (sx[sX] > 0.0f) {                                       \
                    jX = sX; rX = __ldg(rtt + base + sX); break;           \
                }                                                          \
                snxt[sX] = (unsigned short)KILL16;                         \
            }

        ADVANCE(kA, sA, jA, rA, actA, 8)
        ADVANCE(kB, sB, jB, rB, actB, 16)

        while (actA || actB) {
            float a0, a1, a2, a3, b0, b1, b2, b3;
            if (actA) { a0 = sd[jA]; a1 = sd[jA+1]; a2 = sd[jA+2]; a3 = sd[jA+3]; }
            if (actB) { b0 = sd[jB]; b1 = sd[jB+1]; b2 = sd[jB+2]; b3 = sd[jB+3]; }
            if (actA) {                           // exact sequential chain (A)
                int e = 0;
                rA = __fsub_rn(rA, a0);
                if (rA <= 0.0f) e = jA + 1; else {
                rA = __fsub_rn(rA, a1);
                if (rA <= 0.0f) e = jA + 2; else {
                rA = __fsub_rn(rA, a2);
                if (rA <= 0.0f) e = jA + 3; else {
                rA = __fsub_rn(rA, a3);
                if (rA <= 0.0f) e = jA + 4; } } }
                if (e) {                          // 1e30 pads bound e <= SS+3
                    snxt[sA] = (unsigned short)(e < SS ? e : SS);
                    ADVANCE(kA, sA, jA, rA, actA, 8)
                } else jA += 4;
            }
            if (actB) {                           // exact sequential chain (B)
                int e = 0;
                rB = __fsub_rn(rB, b0);
                if (rB <= 0.0f) e = jB + 1; else {
                rB = __fsub_rn(rB, b1);
                if (rB <= 0.0f) e = jB + 2; else {
                rB = __fsub_rn(rB, b2);
                if (rB <= 0.0f) e = jB + 3; else {
                rB = __fsub_rn(rB, b3);
                if (rB <= 0.0f) e = jB + 4; } } }
                if (e) {
                    snxt[sB] = (unsigned short)(e < SS ? e : SS);
                    ADVANCE(kB, sB, jB, rB, actB, 16)
                } else jB += 4;
            }
        }
        #undef ADVANCE
    }
    __syncthreads();

    // ---- P2: exit table via warp-shfl pointer doubling -------------------
    unsigned short* sexit = (unsigned short*)sd;       // dly is dead
    {
        const int wid  = tid >> 5;
        const int lane = tid & 31;
        for (int c = wid; c < NCHUNK; c += NT / 32) {  // 16 chunks per warp
            const int cbase = c * CHUNK;
            const int cend  = cbase + CHUNK;
            unsigned short w = snxt[cbase + lane];
            int E = (w & KILL16) ? SS : (int)w;        // kill -> chain dies
            #pragma unroll
            for (int step = 0; step < 5; step++) {     // 2^5 >= CHUNK
                int val = __shfl_sync(0xffffffffu, E, E & 31);
                E = (E < cend) ? val : E;              // E >= cbase always
            }
            sexit[cbase + lane] = (unsigned short)E;
        }
    }
    __syncthreads();

    // ---- P3: serial top walk (<= NCHUNK hops, branchy) -------------------
    if (tid == 0) {
        int pos = 0;
        #pragma unroll 4
        for (int c = 0; c < NCHUNK; c++) {
            senter[c] = (unsigned short)pos;
            if (pos < (c + 1) * CHUNK) pos = sexit[pos];
        }
    }
    __syncthreads();

    // ---- P4: per-chunk counts + per-burst (nf, rem) cache ----------------
    unsigned long long lburst[CHUNK];            // local mem, seq push/pop
    int cnt = 0, nb = 0;
    if (tid < NCHUNK) {
        const int end = (tid + 1) * CHUNK;
        int s = senter[tid];
        while (s < end) {
            unsigned short w = snxt[s];
            if (w & KILL16) break;
            const int e1 = (int)w;
            float buf = burst_sum(sx, s, e1);
            int nf = (int)ceilf(__fdiv_rn(buf, MSSF)) - 1;
            if (nf < 0) nf = 0;
            float rem = __fsub_rn(buf, __fmul_rn((float)nf, MSSF));
            cnt += nf + (rem > 0.0f ? 1 : 0);
            lburst[nb++] = ((unsigned long long)__float_as_uint(rem) << 32)
                         | (unsigned int)nf;
            s = e1;
        }
    }
    __syncthreads();   // sexit dead after this point; sd becomes outrow

    // ---- P5: warp-shfl exclusive scan of chunk counts --------------------
    int inc = cnt;
    if (tid < NCHUNK) {
        const int lane = tid & 31;
        #pragma unroll
        for (int d = 1; d < 32; d <<= 1) {
            int n = __shfl_up_sync(0xffffffffu, inc, d);
            if (lane >= d) inc += n;
        }
        if (lane == 31) swsum[tid >> 5] = inc;          // warp inclusive total
    }
    __syncthreads();

    // ---- P6: pure emission of cached bursts + grand total ----------------
    float* outrow = sd;
    if (tid < NCHUNK) {
        int o = inc - cnt;                              // exclusive within warp
        #pragma unroll
        for (int k = 0; k < NCHUNK / 32; k++)
            if (k < (tid >> 5)) o += swsum[k];
        for (int i = 0; i < nb; i++) {
            unsigned long long v = lburst[i];
            int nf    = (int)(unsigned int)(v & 0xFFFFFFFFu);
            float rem = __uint_as_float((unsigned int)(v >> 32));
            int lim = nf;
            if (o + lim > SS) lim = SS - o;             // truncation (may be <=0)
            for (int k = 0; k < lim; k++) outrow[o + k] = MSSF;
            if (rem > 0.0f && o + nf < SS) outrow[o + nf] = rem;
            o += nf + (rem > 0.0f ? 1 : 0);             // slots [o,o+cnt) dense
        }
    } else if (tid == NCHUNK) {
        int t = 0;
        #pragma unroll
        for (int k = 0; k < NCHUNK / 32; k++) t += swsum[k];
        s_total = (t < SS) ? t : SS;
    }
    __syncthreads();

    // ---- P7: store (tail implicitly zero) --------------------------------
    {
        const int total = s_total;                      // valid range [0, total)
        float4* o4 = (float4*)(out + base);
        const float4* s4 = (const float4*)outrow;
        #pragma unroll
        for (int i = tid; i < SS / 4; i += NT) {
            int e0 = i * 4;
            float4 v;
            if (e0 + 3 < total) {
                v = s4[i];
            } else if (e0 >= total) {
                v = make_float4(0.0f, 0.0f, 0.0f, 0.0f);
            } else {
                v.x = (e0     < total) ? outrow[e0]     : 0.0f;
                v.y = (e0 + 1 < total) ? outrow[e0 + 1] : 0.0f;
                v.z = (e0 + 2 < total) ? outrow[e0 + 2] : 0.0f;
                v.w = (e0 + 3 < total) ? outrow[e0 + 3] : 0.0f;
            }
            o4[i] = v;
        }
    }
}

extern "C" void kernel_launch(void* const* d_in, const int* in_sizes, int n_in,
                              void* d_out, int out_size)
{
    const float* x   = (const float*)d_in[0];
    const float* dly = (const float*)d_in[1];
    const float* rtt = (const float*)d_in[2];
    float* out = (float*)d_out;

    int B = in_sizes[0] / SS;
    traffic_kernel<<<B, NT>>>(x, dly, rtt, out);
}

// round 10
// speedup vs baseline: 1.0747x; 1.0747x over previous
#include <cuda_runtime.h>
#include <cuda_bf16.h>

// TrafficAugmentation [B=2048, S=4096] -> [B, S, 1] f32.
//
// Per row (one block, NT=256, 5 blocks/SM, static grid = B):
//  P0: stage x, dly into SMEM (float4).
//  P1: per-position delay countdown, 2 interleaved walks per thread.
//      Fast path: 4-wide fsub chain + ONE terminal compare; on the
//      terminating batch, replay the identical chain to resolve the
//      crossing element (bit-exact) -> snxt[s] (u16 burst-end | kill).
//  P2: per 32-chunk exit table via warp-shfl pointer doubling.
//  P3: serial top walk (<=128 hops) -> chain entry per chunk.
//  P4: per-chunk output-slot counts; caches (nf, rem) per burst locally.
//  P5: warp-shfl exclusive scan of chunk counts.
//  P6: pure emission of cached bursts at scanned offsets (dense, disjoint).
//  P7: store outrow[i] for i < total, else 0.

#define SS     4096
#define CHUNK  32
#define NCHUNK (SS / CHUNK)     // 128
#define MSSF   1448.0f
#define KILL16 0x8000u
#define NT     256

// Exact index-ordered sum of sx[s0..e1) via aligned float4 LDS loads;
// fp op order identical to the scalar loop (predicated edges).
__device__ __forceinline__ float burst_sum(const float* __restrict__ sxp,
                                           int s0, int e1)
{
    const float4* v4 = (const float4*)sxp;
    float buf = 0.0f;
    for (int jb = (s0 & ~3); jb < e1; jb += 4) {
        float4 v = v4[jb >> 2];
        if (jb     >= s0)                 buf = __fadd_rn(buf, v.x);
        if (jb + 1 >= s0 && jb + 1 < e1)  buf = __fadd_rn(buf, v.y);
        if (jb + 2 >= s0 && jb + 2 < e1)  buf = __fadd_rn(buf, v.z);
        if (jb + 3 >= s0 && jb + 3 < e1)  buf = __fadd_rn(buf, v.w);
    }
    return buf;
}

// Resolve which of the 4 chain steps crossed zero; replays the identical
// __fsub_rn sequence from the batch-entry value (bit-exact).
__device__ __forceinline__ int resolve4(float r, float d0, float d1,
                                        float d2, float d3, int j)
{
    r = __fsub_rn(r, d0); if (r <= 0.0f) return j + 1;
    r = __fsub_rn(r, d1); if (r <= 0.0f) return j + 2;
    r = __fsub_rn(r, d2); if (r <= 0.0f) return j + 3;
    return j + 4;   // caller guarantees full-chain value <= 0
}

__global__ __launch_bounds__(NT, 5)
void traffic_kernel(const float* __restrict__ x,
                    const float* __restrict__ dly,
                    const float* __restrict__ rtt,
                    float* __restrict__ out)
{
    __shared__ __align__(16) float sx[SS + 4];   // x row + 0 pads
    __shared__ __align__(16) float sd[SS + 4];   // dly row + 1e30 pads; later:
                                                 //  P2/P3: exit table (u16)
                                                 //  P6/P7: output row (f32)
    __shared__ unsigned short snxt[SS];          // burst-end | kill
    __shared__ unsigned short senter[NCHUNK];    // chain entry per chunk
    __shared__ int swsum[NCHUNK / 32];           // per-warp count totals
    __shared__ int s_total;                      // grand output count

    const int row  = blockIdx.x;
    const size_t base = (size_t)row * SS;
    const int tid = threadIdx.x;

    // ---- P0: stage inputs ------------------------------------------------
    {
        const float4* x4 = (const float4*)(x + base);
        const float4* d4 = (const float4*)(dly + base);
        float4* sx4 = (float4*)sx;
        float4* sd4 = (float4*)sd;
        #pragma unroll
        for (int i = tid; i < SS / 4; i += NT) { sx4[i] = x4[i]; sd4[i] = d4[i]; }
        if (tid < 4) { sx[SS + tid] = 0.0f; sd[SS + tid] = 1e30f; }
    }
    __syncthreads();

    // ---- P1: burst ends, paired walks, single-compare fast path ----------
    #pragma unroll 1
    for (int k = 0; k < SS / NT; k += 2) {
        const int sA = tid + k * NT;
        const int sB = sA + NT;
        float rA = __ldg(rtt + base + sA);       // issue both early (MLP)
        float rB = __ldg(rtt + base + sB);
        const bool aliveA = (sx[sA] > 0.0f);
        const bool aliveB = (sx[sB] > 0.0f);
        int jA = sA, jB = sB;
        int endA = SS, endB = SS;
        bool runA = aliveA, runB = aliveB;
        while (runA | runB) {
            float a0, a1, a2, a3, b0, b1, b2, b3;
            if (runA) { a0 = sd[jA]; a1 = sd[jA+1]; a2 = sd[jA+2]; a3 = sd[jA+3]; }
            if (runB) { b0 = sd[jB]; b1 = sd[jB+1]; b2 = sd[jB+2]; b3 = sd[jB+3]; }
            if (runA) {
                // full-batch chain (exact sequential values)
                float t = __fsub_rn(rA, a0);
                t = __fsub_rn(t, a1);
                t = __fsub_rn(t, a2);
                t = __fsub_rn(t, a3);
                if (t <= 0.0f) {                  // rare: resolve exactly
                    endA = resolve4(rA, a0, a1, a2, a3, jA);
                    runA = false;
                } else { rA = t; jA += 4; }
                // 1e30 pads at sd[SS..] force termination just past SS
            }
            if (runB) {
                float t = __fsub_rn(rB, b0);
                t = __fsub_rn(t, b1);
                t = __fsub_rn(t, b2);
                t = __fsub_rn(t, b3);
                if (t <= 0.0f) {
                    endB = resolve4(rB, b0, b1, b2, b3, jB);
                    runB = false;
                } else { rB = t; jB += 4; }
            }
        }
        snxt[sA] = aliveA ? (unsigned short)(endA < SS ? endA : SS)
                          : (unsigned short)KILL16;
        snxt[sB] = aliveB ? (unsigned short)(endB < SS ? endB : SS)
                          : (unsigned short)KILL16;
    }
    __syncthreads();

    // ---- P2: exit table via warp-shfl pointer doubling -------------------
    unsigned short* sexit = (unsigned short*)sd;       // dly is dead
    {
        const int wid  = tid >> 5;
        const int lane = tid & 31;
        for (int c = wid; c < NCHUNK; c += NT / 32) {  // 16 chunks per warp
            const int cbase = c * CHUNK;
            const int cend  = cbase + CHUNK;
            unsigned short w = snxt[cbase + lane];
            int E = (w & KILL16) ? SS : (int)w;        // kill -> chain dies
            #pragma unroll
            for (int step = 0; step < 5; step++) {     // 2^5 >= CHUNK
                int val = __shfl_sync(0xffffffffu, E, E & 31);
                E = (E < cend) ? val : E;              // E >= cbase always
            }
            sexit[cbase + lane] = (unsigned short)E;
        }
    }
    __syncthreads();

    // ---- P3: serial top walk (<= NCHUNK hops, branchy) -------------------
    if (tid == 0) {
        int pos = 0;
        #pragma unroll 4
        for (int c = 0; c < NCHUNK; c++) {
            senter[c] = (unsigned short)pos;
            if (pos < (c + 1) * CHUNK) pos = sexit[pos];
        }
    }
    __syncthreads();

    // ---- P4: per-chunk counts + per-burst (nf, rem) cache ----------------
    unsigned long long lburst[CHUNK];            // local mem, seq push/pop
    int cnt = 0, nb = 0;
    if (tid < NCHUNK) {
        const int end = (tid + 1) * CHUNK;
        int s = senter[tid];
        while (s < end) {
            unsigned short w = snxt[s];
            if (w & KILL16) break;
            const int e1 = (int)w;
            float buf = burst_sum(sx, s, e1);
            int nf = (int)ceilf(__fdiv_rn(buf, MSSF)) - 1;
            if (nf < 0) nf = 0;
            float rem = __fsub_rn(buf, __fmul_rn((float)nf, MSSF));
            cnt += nf + (rem > 0.0f ? 1 : 0);
            lburst[nb++] = ((unsigned long long)__float_as_uint(rem) << 32)
                         | (unsigned int)nf;
            s = e1;
        }
    }
    __syncthreads();   // sexit dead after this point; sd becomes outrow

    // ---- P5: warp-shfl exclusive scan of chunk counts --------------------
    int inc = cnt;
    if (tid < NCHUNK) {
        const int lane = tid & 31;
        #pragma unroll
        for (int d = 1; d < 32; d <<= 1) {
            int n = __shfl_up_sync(0xffffffffu, inc, d);
            if (lane >= d) inc += n;
        }
        if (lane == 31) swsum[tid >> 5] = inc;          // warp inclusive total
    }
    __syncthreads();

    // ---- P6: pure emission of cached bursts + grand total ----------------
    float* outrow = sd;
    if (tid < NCHUNK) {
        int o = inc - cnt;                              // exclusive within warp
        #pragma unroll
        for (int k = 0; k < NCHUNK / 32; k++)
            if (k < (tid >> 5)) o += swsum[k];
        for (int i = 0; i < nb; i++) {
            unsigned long long v = lburst[i];
            int nf    = (int)(unsigned int)(v & 0xFFFFFFFFu);
            float rem = __uint_as_float((unsigned int)(v >> 32));
            int lim = nf;
            if (o + lim > SS) lim = SS - o;             // truncation (may be <=0)
            for (int k = 0; k < lim; k++) outrow[o + k] = MSSF;
            if (rem > 0.0f && o + nf < SS) outrow[o + nf] = rem;
            o += nf + (rem > 0.0f ? 1 : 0);             // slots [o,o+cnt) dense
        }
    } else if (tid == NCHUNK) {
        int t = 0;
        #pragma unroll
        for (int k = 0; k < NCHUNK / 32; k++) t += swsum[k];
        s_total = (t < SS) ? t : SS;
    }
    __syncthreads();

    // ---- P7: store (tail implicitly zero) --------------------------------
    {
        const int total = s_total;                      // valid range [0, total)
        float4* o4 = (float4*)(out + base);
        const float4* s4 = (const float4*)outrow;
        #pragma unroll
        for (int i = tid; i < SS / 4; i += NT) {
            int e0 = i * 4;
            float4 v;
            if (e0 + 3 < total) {
                v = s4[i];
            } else if (e0 >= total) {
                v = make_float4(0.0f, 0.0f, 0.0f, 0.0f);
            } else {
                v.x = (e0     < total) ? outrow[e0]     : 0.0f;
                v.y = (e0 + 1 < total) ? outrow[e0 + 1] : 0.0f;
                v.z = (e0 + 2 < total) ? outrow[e0 + 2] : 0.0f;
                v.w = (e0 + 3 < total) ? outrow[e0 + 3] : 0.0f;
            }
            o4[i] = v;
        }
    }
}

extern "C" void kernel_launch(void* const* d_in, const int* in_sizes, int n_in,
                              void* d_out, int out_size)
{
    const float* x   = (const float*)d_in[0];
    const float* dly = (const float*)d_in[1];
    const float* rtt = (const float*)d_in[2];
    float* out = (float*)d_out;

    int B = in_sizes[0] / SS;
    traffic_kernel<<<B, NT>>>(x, dly, rtt, out);
}

// round 11
// speedup vs baseline: 1.2060x; 1.1222x over previous
#include <cuda_runtime.h>
#include <cuda_bf16.h>

// TrafficAugmentation [B=2048, S=4096] -> [B, S, 1] f32.
//
// Per row (one block, NT=256, 5 blocks/SM, static grid = B):
//  P0: stage x, dly into SMEM (float4).
//  P1: per-position delay countdown, 2 interleaved walks per thread,
//      FULLY BRANCHLESS body (selects only; single loop branch).
//      Chain is strictly decreasing (delays > 0), so the crossing index
//      within a batch is j + 1 + #(positive prefixes) -- no control flow.
//      Exact sequential __fsub_rn order -> bit-identical to reference.
//  P2: per 32-chunk exit table via warp-shfl pointer doubling.
//  P3: serial top walk (<=128 hops) -> chain entry per chunk.
//  P4: per-chunk output-slot counts; caches (nf, rem) per burst locally.
//  P5: warp-shfl exclusive scan of chunk counts.
//  P6: pure emission of cached bursts at scanned offsets (dense, disjoint).
//  P7: store outrow[i] for i < total, else 0.

#define SS     4096
#define CHUNK  32
#define NCHUNK (SS / CHUNK)     // 128
#define MSSF   1448.0f
#define KILL16 0x8000u
#define NT     256

// Exact index-ordered sum of sx[s0..e1) via aligned float4 LDS loads;
// fp op order identical to the scalar loop (predicated edges).
__device__ __forceinline__ float burst_sum(const float* __restrict__ sxp,
                                           int s0, int e1)
{
    const float4* v4 = (const float4*)sxp;
    float buf = 0.0f;
    for (int jb = (s0 & ~3); jb < e1; jb += 4) {
        float4 v = v4[jb >> 2];
        if (jb     >= s0)                 buf = __fadd_rn(buf, v.x);
        if (jb + 1 >= s0 && jb + 1 < e1)  buf = __fadd_rn(buf, v.y);
        if (jb + 2 >= s0 && jb + 2 < e1)  buf = __fadd_rn(buf, v.z);
        if (jb + 3 >= s0 && jb + 3 < e1)  buf = __fadd_rn(buf, v.w);
    }
    return buf;
}

__global__ __launch_bounds__(NT, 5)
void traffic_kernel(const float* __restrict__ x,
                    const float* __restrict__ dly,
                    const float* __restrict__ rtt,
                    float* __restrict__ out)
{
    __shared__ __align__(16) float sx[SS + 4];   // x row + 0 pads
    __shared__ __align__(16) float sd[SS + 4];   // dly row + 1e30 pads; later:
                                                 //  P2/P3: exit table (u16)
                                                 //  P6/P7: output row (f32)
    __shared__ unsigned short snxt[SS];          // burst-end | kill
    __shared__ unsigned short senter[NCHUNK];    // chain entry per chunk
    __shared__ int swsum[NCHUNK / 32];           // per-warp count totals
    __shared__ int s_total;                      // grand output count

    const int row  = blockIdx.x;
    const size_t base = (size_t)row * SS;
    const int tid = threadIdx.x;

    // ---- P0: stage inputs ------------------------------------------------
    {
        const float4* x4 = (const float4*)(x + base);
        const float4* d4 = (const float4*)(dly + base);
        float4* sx4 = (float4*)sx;
        float4* sd4 = (float4*)sd;
        #pragma unroll
        for (int i = tid; i < SS / 4; i += NT) { sx4[i] = x4[i]; sd4[i] = d4[i]; }
        if (tid < 4) { sx[SS + tid] = 0.0f; sd[SS + tid] = 1e30f; }
    }
    __syncthreads();

    // ---- P1: burst ends, paired walks, branchless body -------------------
    #pragma unroll 1
    for (int k = 0; k < SS / NT; k += 2) {
        const int sA = tid + k * NT;
        const int sB = sA + NT;
        float rA = __ldg(rtt + base + sA);       // issue both early (MLP)
        float rB = __ldg(rtt + base + sB);
        const bool aliveA = (sx[sA] > 0.0f);
        const bool aliveB = (sx[sB] > 0.0f);
        int jA = sA, jB = sB;
        int endA = SS, endB = SS;
        int doneA = !aliveA, doneB = !aliveB;
        while (!(doneA & doneB)) {
            // Frozen walks recompute their terminal batch idempotently
            // (j frozen -> same loads -> same chain -> stay done).
            float a0 = sd[jA], a1 = sd[jA+1], a2 = sd[jA+2], a3 = sd[jA+3];
            float b0 = sd[jB], b1 = sd[jB+1], b2 = sd[jB+2], b3 = sd[jB+3];
            // exact sequential chains (strictly decreasing)
            float A1 = __fsub_rn(rA, a0);
            float A2 = __fsub_rn(A1, a1);
            float A3 = __fsub_rn(A2, a2);
            float A4 = __fsub_rn(A3, a3);
            float B1 = __fsub_rn(rB, b0);
            float B2 = __fsub_rn(B1, b1);
            float B3 = __fsub_rn(B2, b2);
            float B4 = __fsub_rn(B3, b3);
            const int tA = (A4 <= 0.0f);         // batch terminates?
            const int tB = (B4 <= 0.0f);
            // crossing index: monotone chain -> count positive prefixes
            const int cA = jA + 1 + (int)(A1 > 0.0f) + (int)(A2 > 0.0f)
                                  + (int)(A3 > 0.0f);
            const int cB = jB + 1 + (int)(B1 > 0.0f) + (int)(B2 > 0.0f)
                                  + (int)(B3 > 0.0f);
            const int newA = tA & ~doneA;        // newly terminated this iter
            const int newB = tB & ~doneB;
            endA = newA ? cA : endA;             // selects only
            endB = newB ? cB : endB;
            const int frzA = doneA | tA;         // freeze state when done/term
            const int frzB = doneB | tB;
            jA = frzA ? jA : jA + 4;
            jB = frzB ? jB : jB + 4;
            rA = frzA ? rA : A4;
            rB = frzB ? rB : B4;
            doneA = frzA;
            doneB = frzB;
            // 1e30 pads at sd[SS..SS+3] force termination just past SS,
            // so jA/jB never read beyond sd[SS+2].
        }
        snxt[sA] = aliveA ? (unsigned short)(endA < SS ? endA : SS)
                          : (unsigned short)KILL16;
        snxt[sB] = aliveB ? (unsigned short)(endB < SS ? endB : SS)
                          : (unsigned short)KILL16;
    }
    __syncthreads();

    // ---- P2: exit table via warp-shfl pointer doubling -------------------
    unsigned short* sexit = (unsigned short*)sd;       // dly is dead
    {
        const int wid  = tid >> 5;
        const int lane = tid & 31;
        for (int c = wid; c < NCHUNK; c += NT / 32) {  // 16 chunks per warp
            const int cbase = c * CHUNK;
            const int cend  = cbase + CHUNK;
            unsigned short w = snxt[cbase + lane];
            int E = (w & KILL16) ? SS : (int)w;        // kill -> chain dies
            #pragma unroll
            for (int step = 0; step < 5; step++) {     // 2^5 >= CHUNK
                int val = __shfl_sync(0xffffffffu, E, E & 31);
                E = (E < cend) ? val : E;              // E >= cbase always
            }
            sexit[cbase + lane] = (unsigned short)E;
        }
    }
    __syncthreads();

    // ---- P3: serial top walk (<= NCHUNK hops, branchy) -------------------
    if (tid == 0) {
        int pos = 0;
        #pragma unroll 4
        for (int c = 0; c < NCHUNK; c++) {
            senter[c] = (unsigned short)pos;
            if (pos < (c + 1) * CHUNK) pos = sexit[pos];
        }
    }
    __syncthreads();

    // ---- P4: per-chunk counts + per-burst (nf, rem) cache ----------------
    unsigned long long lburst[CHUNK];            // local mem, seq push/pop
    int cnt = 0, nb = 0;
    if (tid < NCHUNK) {
        const int end = (tid + 1) * CHUNK;
        int s = senter[tid];
        while (s < end) {
            unsigned short w = snxt[s];
            if (w & KILL16) break;
            const int e1 = (int)w;
            float buf = burst_sum(sx, s, e1);
            int nf = (int)ceilf(__fdiv_rn(buf, MSSF)) - 1;
            if (nf < 0) nf = 0;
            float rem = __fsub_rn(buf, __fmul_rn((float)nf, MSSF));
            cnt += nf + (rem > 0.0f ? 1 : 0);
            lburst[nb++] = ((unsigned long long)__float_as_uint(rem) << 32)
                         | (unsigned int)nf;
            s = e1;
        }
    }
    __syncthreads();   // sexit dead after this point; sd becomes outrow

    // ---- P5: warp-shfl exclusive scan of chunk counts --------------------
    int inc = cnt;
    if (tid < NCHUNK) {
        const int lane = tid & 31;
        #pragma unroll
        for (int d = 1; d < 32; d <<= 1) {
            int n = __shfl_up_sync(0xffffffffu, inc, d);
            if (lane >= d) inc += n;
        }
        if (lane == 31) swsum[tid >> 5] = inc;          // warp inclusive total
    }
    __syncthreads();

    // ---- P6: pure emission of cached bursts + grand total ----------------
    float* outrow = sd;
    if (tid < NCHUNK) {
        int o = inc - cnt;                              // exclusive within warp
        #pragma unroll
        for (int k = 0; k < NCHUNK / 32; k++)
            if (k < (tid >> 5)) o += swsum[k];
        for (int i = 0; i < nb; i++) {
            unsigned long long v = lburst[i];
            int nf    = (int)(unsigned int)(v & 0xFFFFFFFFu);
            float rem = __uint_as_float((unsigned int)(v >> 32));
            int lim = nf;
            if (o + lim > SS) lim = SS - o;             // truncation (may be <=0)
            for (int k = 0; k < lim; k++) outrow[o + k] = MSSF;
            if (rem > 0.0f && o + nf < SS) outrow[o + nf] = rem;
            o += nf + (rem > 0.0f ? 1 : 0);             // slots [o,o+cnt) dense
        }
    } else if (tid == NCHUNK) {
        int t = 0;
        #pragma unroll
        for (int k = 0; k < NCHUNK / 32; k++) t += swsum[k];
        s_total = (t < SS) ? t : SS;
    }
    __syncthreads();

    // ---- P7: store (tail implicitly zero) --------------------------------
    {
        const int total = s_total;                      // valid range [0, total)
        float4* o4 = (float4*)(out + base);
        const float4* s4 = (const float4*)outrow;
        #pragma unroll
        for (int i = tid; i < SS / 4; i += NT) {
            int e0 = i * 4;
            float4 v;
            if (e0 + 3 < total) {
                v = s4[i];
            } else if (e0 >= total) {
                v = make_float4(0.0f, 0.0f, 0.0f, 0.0f);
            } else {
                v.x = (e0     < total) ? outrow[e0]     : 0.0f;
                v.y = (e0 + 1 < total) ? outrow[e0 + 1] : 0.0f;
                v.z = (e0 + 2 < total) ? outrow[e0 + 2] : 0.0f;
                v.w = (e0 + 3 < total) ? outrow[e0 + 3] : 0.0f;
            }
            o4[i] = v;
        }
    }
}

extern "C" void kernel_launch(void* const* d_in, const int* in_sizes, int n_in,
                              void* d_out, int out_size)
{
    const float* x   = (const float*)d_in[0];
    const float* dly = (const float*)d_in[1];
    const float* rtt = (const float*)d_in[2];
    float* out = (float*)d_out;

    int B = in_sizes[0] / SS;
    traffic_kernel<<<B, NT>>>(x, dly, rtt, out);
}